// round 7
// baseline (speedup 1.0000x reference)
#include <cuda_runtime.h>
#include <cuda_bf16.h>
#include <math.h>

// ---------------------------------------------------------------------------
// Problem constants (fixed by the dataset)
// ---------------------------------------------------------------------------
#define MAX_NODES 50000
#define MAX_EDGES 800000
#define DHID      256
#define DH4       64          // DHID / 4
#define NGRAPHS   64
#define DIN       768

// ---------------------------------------------------------------------------
// Scratch (static device globals -- no runtime allocation allowed).
// 16B-aligned so float4 (LDG.128/STG.128) access is always legal.
// ---------------------------------------------------------------------------
__device__ __align__(16) float g_h   [MAX_NODES * DHID];   // GEMM output (x @ W)
__device__ __align__(16) float g_agg [MAX_NODES * DHID];   // aggregated / next input
__device__ float g_dinv[MAX_NODES];          // deg^{-1/2} (incl. self loop)
__device__ int   g_edeg[MAX_NODES];          // edge-only in-degree
__device__ int   g_off [MAX_NODES + 1];      // CSR row offsets (by dst)
__device__ int   g_cur [MAX_NODES];          // scatter cursors
__device__ int   g_csr [MAX_EDGES];          // CSR column (src) indices
__device__ float g_pool[NGRAPHS * DHID];     // graph means
__device__ int   g_gstart[NGRAPHS + 1];      // first node index per graph

// ---------------------------------------------------------------------------
// init: zero histogram/cursors, set graph starts to n (sentinel)
// ---------------------------------------------------------------------------
__global__ void init_kernel(int n) {
    int i = blockIdx.x * blockDim.x + threadIdx.x;
    if (i < n) { g_edeg[i] = 0; g_cur[i] = 0; }
    if (i <= NGRAPHS) g_gstart[i] = n;
}

__global__ void hist_kernel(const int* __restrict__ dst, int E) {
    int i = blockIdx.x * blockDim.x + threadIdx.x;
    if (i < E) atomicAdd(&g_edeg[dst[i]], 1);
}

__global__ void dinv_kernel(int n) {
    int i = blockIdx.x * blockDim.x + threadIdx.x;
    if (i < n) g_dinv[i] = rsqrtf((float)(g_edeg[i] + 1));
}

// ---------------------------------------------------------------------------
// Single-block exclusive scan of g_edeg -> g_off (1024 threads, chunked)
// ---------------------------------------------------------------------------
__global__ __launch_bounds__(1024)
void scan_kernel(int n) {
    __shared__ int wsum[32];
    __shared__ int carry;
    const int tid = threadIdx.x;
    if (tid == 0) carry = 0;
    __syncthreads();

    for (int base = 0; base < n; base += 1024) {
        int i = base + tid;
        int v = (i < n) ? g_edeg[i] : 0;
        int x = v;
        #pragma unroll
        for (int ofs = 1; ofs < 32; ofs <<= 1) {
            int y = __shfl_up_sync(0xFFFFFFFFu, x, ofs);
            if ((tid & 31) >= ofs) x += y;
        }
        if ((tid & 31) == 31) wsum[tid >> 5] = x;
        __syncthreads();
        if (tid < 32) {
            int w = wsum[tid];
            #pragma unroll
            for (int ofs = 1; ofs < 32; ofs <<= 1) {
                int y = __shfl_up_sync(0xFFFFFFFFu, w, ofs);
                if (tid >= ofs) w += y;
            }
            wsum[tid] = w;
        }
        __syncthreads();
        int incl = x + ((tid >= 32) ? wsum[(tid >> 5) - 1] : 0);
        int c = carry;
        if (i < n) g_off[i] = c + incl - v;     // exclusive
        __syncthreads();
        if (tid == 1023) carry = c + incl;      // chunk total
        __syncthreads();
    }
    if (tid == 0) g_off[n] = carry;
}

__global__ void scatter_kernel(const int* __restrict__ src,
                               const int* __restrict__ dst, int E) {
    int i = blockIdx.x * blockDim.x + threadIdx.x;
    if (i < E) {
        int d = dst[i];
        int pos = g_off[d] + atomicAdd(&g_cur[d], 1);
        g_csr[pos] = src[i];
    }
}

// graph start indices (batch is sorted)
__global__ void gmin_kernel(const int* __restrict__ batch, int n) {
    int i = blockIdx.x * blockDim.x + threadIdx.x;
    if (i < n) atomicMin(&g_gstart[batch[i]], i);
}

__global__ void gfix_kernel(int n) {
    if (threadIdx.x == 0 && blockIdx.x == 0) {
        g_gstart[NGRAPHS] = n;
        for (int g = NGRAPHS - 1; g >= 0; g--)
            if (g_gstart[g] > g_gstart[g + 1]) g_gstart[g] = g_gstart[g + 1];
    }
}

// ---------------------------------------------------------------------------
// Tiled fp32 GEMM: g_h = A @ B. A = external x (layer 1) or g_agg.
// BM=128 BN=64 BK=16, 256 threads, 8x4 register tile.
// ---------------------------------------------------------------------------
#define BM 128
#define BN 64
#define BK 16

__global__ __launch_bounds__(256)
void gemm_kernel(const float* __restrict__ Aext, int use_ext,
                 const float* __restrict__ B, int M, int K, int N) {
    const float* __restrict__ A = use_ext ? Aext : (const float*)g_agg;
    float* __restrict__ C = g_h;

    __shared__ float As[BK][BM + 1];
    __shared__ float Bs[BK][BN + 1];

    const int tid = threadIdx.x;
    const int tx  = tid & 15;
    const int ty  = tid >> 4;
    const int row0 = blockIdx.y * BM;
    const int col0 = blockIdx.x * BN;

    float acc[8][4];
    #pragma unroll
    for (int i = 0; i < 8; i++)
        #pragma unroll
        for (int j = 0; j < 4; j++) acc[i][j] = 0.f;

    for (int k0 = 0; k0 < K; k0 += BK) {
        #pragma unroll
        for (int l = 0; l < 8; l++) {
            int idx = tid + l * 256;
            int r = idx >> 4, c = idx & 15;
            int gr = row0 + r;
            As[c][r] = (gr < M) ? A[(size_t)gr * K + k0 + c] : 0.f;
        }
        #pragma unroll
        for (int l = 0; l < 4; l++) {
            int idx = tid + l * 256;
            int r = idx >> 6, c = idx & 63;
            Bs[r][c] = B[(size_t)(k0 + r) * N + col0 + c];
        }
        __syncthreads();

        #pragma unroll
        for (int kk = 0; kk < BK; kk++) {
            float a[8], b[4];
            #pragma unroll
            for (int i = 0; i < 8; i++) a[i] = As[kk][ty * 8 + i];
            #pragma unroll
            for (int j = 0; j < 4; j++) b[j] = Bs[kk][tx * 4 + j];
            #pragma unroll
            for (int i = 0; i < 8; i++)
                #pragma unroll
                for (int j = 0; j < 4; j++) acc[i][j] += a[i] * b[j];
        }
        __syncthreads();
    }

    #pragma unroll
    for (int i = 0; i < 8; i++) {
        int gr = row0 + ty * 8 + i;
        if (gr < M) {
            #pragma unroll
            for (int j = 0; j < 4; j++)
                C[(size_t)gr * N + col0 + tx * 4 + j] = acc[i][j];
        }
    }
}

// ---------------------------------------------------------------------------
// Fused aggregation: warp per node, atomic-free.
// agg[d] = sum_{s in N(d)} h[s]*dinv[s]*dinv[d] + dinv[d]^2*h[d] + bias (,ReLU)
// Each lane owns 2 float4 (256 floats / 32 lanes).
// ---------------------------------------------------------------------------
__global__ __launch_bounds__(256)
void node_agg_kernel(const float4* __restrict__ bias, int n, int do_relu) {
    int node = (blockIdx.x * blockDim.x + threadIdx.x) >> 5;
    if (node >= n) return;
    int lane = threadIdx.x & 31;

    const float4* __restrict__ h4 = (const float4*)g_h;
    const int beg = g_off[node];
    const int end = g_off[node + 1];
    const float dn = g_dinv[node];

    float4 a0 = make_float4(0.f, 0.f, 0.f, 0.f);
    float4 a1 = make_float4(0.f, 0.f, 0.f, 0.f);

    for (int e = beg; e < end; e++) {
        int s = g_csr[e];
        float nm = dn * g_dinv[s];
        float4 v0 = h4[(size_t)s * DH4 + lane];
        float4 v1 = h4[(size_t)s * DH4 + lane + 32];
        a0.x += v0.x * nm; a0.y += v0.y * nm; a0.z += v0.z * nm; a0.w += v0.w * nm;
        a1.x += v1.x * nm; a1.y += v1.y * nm; a1.z += v1.z * nm; a1.w += v1.w * nm;
    }

    // self loop + bias
    float sl = dn * dn;
    float4 s0 = h4[(size_t)node * DH4 + lane];
    float4 s1 = h4[(size_t)node * DH4 + lane + 32];
    float4 b0 = bias[lane];
    float4 b1 = bias[lane + 32];
    a0.x += s0.x * sl + b0.x; a0.y += s0.y * sl + b0.y;
    a0.z += s0.z * sl + b0.z; a0.w += s0.w * sl + b0.w;
    a1.x += s1.x * sl + b1.x; a1.y += s1.y * sl + b1.y;
    a1.z += s1.z * sl + b1.z; a1.w += s1.w * sl + b1.w;

    if (do_relu) {
        a0.x = fmaxf(a0.x, 0.f); a0.y = fmaxf(a0.y, 0.f);
        a0.z = fmaxf(a0.z, 0.f); a0.w = fmaxf(a0.w, 0.f);
        a1.x = fmaxf(a1.x, 0.f); a1.y = fmaxf(a1.y, 0.f);
        a1.z = fmaxf(a1.z, 0.f); a1.w = fmaxf(a1.w, 0.f);
    }

    float4* agg4 = (float4*)g_agg;
    agg4[(size_t)node * DH4 + lane]      = a0;
    agg4[(size_t)node * DH4 + lane + 32] = a1;
}

// ---------------------------------------------------------------------------
// Mean pool: one block per graph (batch sorted -> contiguous node ranges).
// thread c owns feature c; coalesced loads; atomic-free.
// ---------------------------------------------------------------------------
__global__ __launch_bounds__(DHID)
void pool_kernel() {
    int g = blockIdx.x;
    int c = threadIdx.x;
    int beg = g_gstart[g], end = g_gstart[g + 1];
    float acc = 0.f;
    int i = beg;
    for (; i + 4 <= end; i += 4) {
        acc += g_agg[(size_t)(i + 0) * DHID + c];
        acc += g_agg[(size_t)(i + 1) * DHID + c];
        acc += g_agg[(size_t)(i + 2) * DHID + c];
        acc += g_agg[(size_t)(i + 3) * DHID + c];
    }
    for (; i < end; i++) acc += g_agg[(size_t)i * DHID + c];
    float cnt = (float)(end - beg);
    g_pool[g * DHID + c] = acc / fmaxf(cnt, 1.f);
}

// ---------------------------------------------------------------------------
// Final linear: out[g,d] = pool[g,:] @ Wl[:,d] + bl[d]
// ---------------------------------------------------------------------------
__global__ __launch_bounds__(256)
void final_kernel(const float* __restrict__ Wl, const float* __restrict__ bl,
                  float* __restrict__ out) {
    int d = blockIdx.x * blockDim.x + threadIdx.x;   // 0..767
    int g = blockIdx.y;
    const float* pg = g_pool + g * DHID;
    float acc = 0.f;
    #pragma unroll 8
    for (int c = 0; c < DHID; c++)
        acc += pg[c] * Wl[(size_t)c * DIN + d];
    out[(size_t)g * DIN + d] = acc + bl[d];
}

// ---------------------------------------------------------------------------
// Launch
// ---------------------------------------------------------------------------
extern "C" void kernel_launch(void* const* d_in, const int* in_sizes, int n_in,
                              void* d_out, int out_size) {
    const float* x     = (const float*)d_in[0];
    const int*   ei    = (const int*)d_in[1];     // int32! (JAX x64-disabled)
    const int*   batch = (const int*)d_in[2];     // int32!
    const float* W1 = (const float*)d_in[3];
    const float* b1 = (const float*)d_in[4];
    const float* W2 = (const float*)d_in[5];
    const float* b2 = (const float*)d_in[6];
    const float* W3 = (const float*)d_in[7];
    const float* b3 = (const float*)d_in[8];
    const float* Wl = (const float*)d_in[9];
    const float* bl = (const float*)d_in[10];
    float* out = (float*)d_out;

    const int n = in_sizes[0] / DIN;       // 50000
    const int E = in_sizes[1] / 2;         // 800000
    const int* src = ei;
    const int* dst = ei + E;

    dim3 gemm_grid(DHID / BN, (n + BM - 1) / BM);
    const int agg_grid = (n * 32 + 255) / 256;      // warp per node

    // --- CSR build + normalization ---
    init_kernel<<<(n + 256) / 256, 256>>>(n);
    hist_kernel<<<(E + 255) / 256, 256>>>(dst, E);
    dinv_kernel<<<(n + 255) / 256, 256>>>(n);
    scan_kernel<<<1, 1024>>>(n);
    scatter_kernel<<<(E + 255) / 256, 256>>>(src, dst, E);
    gmin_kernel<<<(n + 255) / 256, 256>>>(batch, n);
    gfix_kernel<<<1, 32>>>(n);

    // --- layer 1 ---
    gemm_kernel<<<gemm_grid, 256>>>(x, 1, W1, n, DIN, DHID);
    node_agg_kernel<<<agg_grid, 256>>>((const float4*)b1, n, 1);

    // --- layer 2 ---
    gemm_kernel<<<gemm_grid, 256>>>(x, 0, W2, n, DHID, DHID);
    node_agg_kernel<<<agg_grid, 256>>>((const float4*)b2, n, 1);

    // --- layer 3 (no relu) ---
    gemm_kernel<<<gemm_grid, 256>>>(x, 0, W3, n, DHID, DHID);
    node_agg_kernel<<<agg_grid, 256>>>((const float4*)b3, n, 0);

    // --- mean pool + head ---
    pool_kernel<<<NGRAPHS, DHID>>>();
    dim3 fgrid(DIN / 256, NGRAPHS);
    final_kernel<<<fgrid, 256>>>(Wl, bl, out);
}

// round 10
// speedup vs baseline: 2.1168x; 2.1168x over previous
#include <cuda_runtime.h>
#include <cuda_bf16.h>
#include <math.h>
#include <stdint.h>

// ---------------------------------------------------------------------------
// Problem constants
// ---------------------------------------------------------------------------
#define MAX_NODES 50000
#define MAX_EDGES 800000
#define DHID      256
#define DH4       64
#define NGRAPHS   64
#define DIN       768
#define MAXB      64          // max scan blocks (50000/1024 = 49)

// ---------------------------------------------------------------------------
// Scratch (static device globals)
// ---------------------------------------------------------------------------
__device__ __align__(16) float g_h   [MAX_NODES * DHID];
__device__ __align__(16) float g_agg [MAX_NODES * DHID];
__device__ float g_dinv[MAX_NODES];
__device__ int   g_edeg[MAX_NODES];
__device__ int   g_off [MAX_NODES + 1];
__device__ int   g_cur [MAX_NODES];
__device__ int   g_csr [MAX_EDGES];
__device__ float g_pool[NGRAPHS * DHID];
__device__ int   g_gstart[NGRAPHS + 1];
__device__ int   g_bsum[MAXB];
__device__ int   g_bofs[MAXB];

// ---------------------------------------------------------------------------
// CSR build helpers
// ---------------------------------------------------------------------------
__global__ void init_kernel(int n) {
    int i = blockIdx.x * blockDim.x + threadIdx.x;
    if (i < n) { g_edeg[i] = 0; g_cur[i] = 0; }
    if (i <= NGRAPHS) g_gstart[i] = n;
}

__global__ void hist_kernel(const int* __restrict__ dst, int E) {
    int i = blockIdx.x * blockDim.x + threadIdx.x;
    if (i < E) atomicAdd(&g_edeg[dst[i]], 1);
}

__global__ void dinv_kernel(int n) {
    int i = blockIdx.x * blockDim.x + threadIdx.x;
    if (i < n) g_dinv[i] = rsqrtf((float)(g_edeg[i] + 1));
}

// --- 3-phase scan: per-block scan -> top scan -> add offsets ---
__global__ __launch_bounds__(1024)
void scan1_kernel(int n) {
    __shared__ int ws[32];
    const int tid = threadIdx.x;
    const int b = blockIdx.x;
    const int i = b * 1024 + tid;
    int v = (i < n) ? g_edeg[i] : 0;
    int x = v;
    #pragma unroll
    for (int ofs = 1; ofs < 32; ofs <<= 1) {
        int y = __shfl_up_sync(0xFFFFFFFFu, x, ofs);
        if ((tid & 31) >= ofs) x += y;
    }
    if ((tid & 31) == 31) ws[tid >> 5] = x;
    __syncthreads();
    if (tid < 32) {
        int w = ws[tid];
        #pragma unroll
        for (int ofs = 1; ofs < 32; ofs <<= 1) {
            int y = __shfl_up_sync(0xFFFFFFFFu, w, ofs);
            if (tid >= ofs) w += y;
        }
        ws[tid] = w;
    }
    __syncthreads();
    int incl = x + ((tid >= 32) ? ws[(tid >> 5) - 1] : 0);
    if (i < n) g_off[i] = incl - v;          // exclusive, no block offset yet
    if (tid == 1023) g_bsum[b] = incl;       // block total
}

__global__ void scan2_kernel(int nb, int n) {
    __shared__ int s[MAXB];
    int tid = threadIdx.x;
    if (tid < nb) s[tid] = g_bsum[tid];
    __syncthreads();
    if (tid == 0) {
        int run = 0;
        for (int b = 0; b < nb; b++) { g_bofs[b] = run; run += s[b]; }
        g_off[n] = run;                       // total edge count
    }
}

__global__ __launch_bounds__(1024)
void scan3_kernel(int n) {
    int i = blockIdx.x * blockDim.x + threadIdx.x;
    if (i < n) g_off[i] += g_bofs[i >> 10];
}

__global__ void scatter_kernel(const int* __restrict__ src,
                               const int* __restrict__ dst, int E) {
    int i = blockIdx.x * blockDim.x + threadIdx.x;
    if (i < E) {
        int d = dst[i];
        int pos = g_off[d] + atomicAdd(&g_cur[d], 1);
        g_csr[pos] = src[i];
    }
}

__global__ void gmin_kernel(const int* __restrict__ batch, int n) {
    int i = blockIdx.x * blockDim.x + threadIdx.x;
    if (i < n) atomicMin(&g_gstart[batch[i]], i);
}

__global__ void gfix_kernel(int n) {
    if (threadIdx.x == 0 && blockIdx.x == 0) {
        g_gstart[NGRAPHS] = n;
        for (int g = NGRAPHS - 1; g >= 0; g--)
            if (g_gstart[g] > g_gstart[g + 1]) g_gstart[g] = g_gstart[g + 1];
    }
}

// ---------------------------------------------------------------------------
// tf32 tensor-core GEMM: g_h = A @ B (A = x or g_agg, row-major; B [K,N] row-major)
// CTA tile 128x128x32, 8 warps, each warp 32x64 via m16n8k8 atoms.
// ---------------------------------------------------------------------------
#define TBM 128
#define TBN 128
#define TBK 32
#define APAD 4      // As row = TBK+APAD = 36 floats
#define BPAD 4      // Bs row = TBN+BPAD = 132 floats

__device__ __forceinline__ uint32_t f2tf32(float f) {
    uint32_t u;
    asm("cvt.rna.tf32.f32 %0, %1;" : "=r"(u) : "f"(f));
    return u;
}

__device__ __forceinline__ void mma_tf32(float* c, const uint32_t* a, const uint32_t* b) {
    asm volatile(
        "mma.sync.aligned.m16n8k8.row.col.f32.tf32.tf32.f32 "
        "{%0,%1,%2,%3}, {%4,%5,%6,%7}, {%8,%9}, {%0,%1,%2,%3};"
        : "+f"(c[0]), "+f"(c[1]), "+f"(c[2]), "+f"(c[3])
        : "r"(a[0]), "r"(a[1]), "r"(a[2]), "r"(a[3]), "r"(b[0]), "r"(b[1]));
}

__global__ __launch_bounds__(256)
void gemm_tc_kernel(const float* __restrict__ Aext, int use_ext,
                    const float* __restrict__ B, int M, int K, int N) {
    const float* __restrict__ A = use_ext ? Aext : (const float*)g_agg;
    float* __restrict__ C = g_h;

    __shared__ float As[TBM][TBK + APAD];   // [m][k], tf32 bit patterns
    __shared__ float Bs[TBK][TBN + BPAD];   // [k][n], tf32 bit patterns

    const int tid  = threadIdx.x;
    const int warp = tid >> 5;
    const int lane = tid & 31;
    const int g    = lane >> 2;             // 0..7
    const int t    = lane & 3;              // 0..3
    const int wm   = warp >> 1;             // 0..3  (M direction)
    const int wn   = warp & 1;              // 0..1  (N direction)
    const int row0 = blockIdx.y * TBM;
    const int col0 = blockIdx.x * TBN;
    const int mbase = wm * 32;
    const int nbase = wn * 64;

    float acc[2][8][4];
    #pragma unroll
    for (int mi = 0; mi < 2; mi++)
        #pragma unroll
        for (int ni = 0; ni < 8; ni++)
            #pragma unroll
            for (int r = 0; r < 4; r++) acc[mi][ni][r] = 0.f;

    for (int k0 = 0; k0 < K; k0 += TBK) {
        // load A tile: 128 rows x 32 k = 1024 float4
        #pragma unroll
        for (int l = 0; l < 4; l++) {
            int f4 = tid + l * 256;
            int r  = f4 >> 3;               // 0..127
            int c4 = f4 & 7;                // 0..7
            int gr = row0 + r;
            float4 v = make_float4(0.f, 0.f, 0.f, 0.f);
            if (gr < M) v = *(const float4*)&A[(size_t)gr * K + k0 + c4 * 4];
            uint4 u;
            u.x = f2tf32(v.x); u.y = f2tf32(v.y); u.z = f2tf32(v.z); u.w = f2tf32(v.w);
            *(uint4*)&As[r][c4 * 4] = u;
        }
        // load B tile: 32 k x 128 n = 1024 float4
        #pragma unroll
        for (int l = 0; l < 4; l++) {
            int f4 = tid + l * 256;
            int r  = f4 >> 5;               // 0..31
            int c4 = f4 & 31;               // 0..31
            float4 v = *(const float4*)&B[(size_t)(k0 + r) * N + col0 + c4 * 4];
            uint4 u;
            u.x = f2tf32(v.x); u.y = f2tf32(v.y); u.z = f2tf32(v.z); u.w = f2tf32(v.w);
            *(uint4*)&Bs[r][c4 * 4] = u;
        }
        __syncthreads();

        #pragma unroll
        for (int k8 = 0; k8 < TBK / 8; k8++) {
            const int kk = k8 * 8;
            uint32_t a[2][4];
            #pragma unroll
            for (int mi = 0; mi < 2; mi++) {
                int r = mbase + mi * 16;
                a[mi][0] = __float_as_uint(As[r + g    ][kk + t    ]);
                a[mi][1] = __float_as_uint(As[r + g + 8][kk + t    ]);
                a[mi][2] = __float_as_uint(As[r + g    ][kk + t + 4]);
                a[mi][3] = __float_as_uint(As[r + g + 8][kk + t + 4]);
            }
            uint32_t b[8][2];
            #pragma unroll
            for (int ni = 0; ni < 8; ni++) {
                int c = nbase + ni * 8 + g;
                b[ni][0] = __float_as_uint(Bs[kk + t    ][c]);
                b[ni][1] = __float_as_uint(Bs[kk + t + 4][c]);
            }
            #pragma unroll
            for (int mi = 0; mi < 2; mi++)
                #pragma unroll
                for (int ni = 0; ni < 8; ni++)
                    mma_tf32(acc[mi][ni], a[mi], b[ni]);
        }
        __syncthreads();
    }

    // writeout: c0,c1 at (g, 2t),(g, 2t+1); c2,c3 at (g+8, ...)
    #pragma unroll
    for (int mi = 0; mi < 2; mi++) {
        int r_lo = row0 + mbase + mi * 16 + g;
        int r_hi = r_lo + 8;
        #pragma unroll
        for (int ni = 0; ni < 8; ni++) {
            int c = col0 + nbase + ni * 8 + 2 * t;
            if (r_lo < M) *(float2*)&C[(size_t)r_lo * N + c] =
                make_float2(acc[mi][ni][0], acc[mi][ni][1]);
            if (r_hi < M) *(float2*)&C[(size_t)r_hi * N + c] =
                make_float2(acc[mi][ni][2], acc[mi][ni][3]);
        }
    }
}

// ---------------------------------------------------------------------------
// Fused aggregation: warp per node, atomic-free
// ---------------------------------------------------------------------------
__global__ __launch_bounds__(256)
void node_agg_kernel(const float4* __restrict__ bias, int n, int do_relu) {
    int node = (blockIdx.x * blockDim.x + threadIdx.x) >> 5;
    if (node >= n) return;
    int lane = threadIdx.x & 31;

    const float4* __restrict__ h4 = (const float4*)g_h;
    const int beg = g_off[node];
    const int end = g_off[node + 1];
    const float dn = g_dinv[node];

    float4 a0 = make_float4(0.f, 0.f, 0.f, 0.f);
    float4 a1 = make_float4(0.f, 0.f, 0.f, 0.f);

    for (int e = beg; e < end; e++) {
        int s = g_csr[e];
        float nm = dn * g_dinv[s];
        float4 v0 = h4[(size_t)s * DH4 + lane];
        float4 v1 = h4[(size_t)s * DH4 + lane + 32];
        a0.x += v0.x * nm; a0.y += v0.y * nm; a0.z += v0.z * nm; a0.w += v0.w * nm;
        a1.x += v1.x * nm; a1.y += v1.y * nm; a1.z += v1.z * nm; a1.w += v1.w * nm;
    }

    float sl = dn * dn;
    float4 s0 = h4[(size_t)node * DH4 + lane];
    float4 s1 = h4[(size_t)node * DH4 + lane + 32];
    float4 b0 = bias[lane];
    float4 b1 = bias[lane + 32];
    a0.x += s0.x * sl + b0.x; a0.y += s0.y * sl + b0.y;
    a0.z += s0.z * sl + b0.z; a0.w += s0.w * sl + b0.w;
    a1.x += s1.x * sl + b1.x; a1.y += s1.y * sl + b1.y;
    a1.z += s1.z * sl + b1.z; a1.w += s1.w * sl + b1.w;

    if (do_relu) {
        a0.x = fmaxf(a0.x, 0.f); a0.y = fmaxf(a0.y, 0.f);
        a0.z = fmaxf(a0.z, 0.f); a0.w = fmaxf(a0.w, 0.f);
        a1.x = fmaxf(a1.x, 0.f); a1.y = fmaxf(a1.y, 0.f);
        a1.z = fmaxf(a1.z, 0.f); a1.w = fmaxf(a1.w, 0.f);
    }

    float4* agg4 = (float4*)g_agg;
    agg4[(size_t)node * DH4 + lane]      = a0;
    agg4[(size_t)node * DH4 + lane + 32] = a1;
}

// ---------------------------------------------------------------------------
// Mean pool + head
// ---------------------------------------------------------------------------
__global__ __launch_bounds__(DHID)
void pool_kernel() {
    int g = blockIdx.x;
    int c = threadIdx.x;
    int beg = g_gstart[g], end = g_gstart[g + 1];
    float acc = 0.f;
    int i = beg;
    for (; i + 4 <= end; i += 4) {
        acc += g_agg[(size_t)(i + 0) * DHID + c];
        acc += g_agg[(size_t)(i + 1) * DHID + c];
        acc += g_agg[(size_t)(i + 2) * DHID + c];
        acc += g_agg[(size_t)(i + 3) * DHID + c];
    }
    for (; i < end; i++) acc += g_agg[(size_t)i * DHID + c];
    float cnt = (float)(end - beg);
    g_pool[g * DHID + c] = acc / fmaxf(cnt, 1.f);
}

__global__ __launch_bounds__(256)
void final_kernel(const float* __restrict__ Wl, const float* __restrict__ bl,
                  float* __restrict__ out) {
    int d = blockIdx.x * blockDim.x + threadIdx.x;
    int g = blockIdx.y;
    const float* pg = g_pool + g * DHID;
    float acc = 0.f;
    #pragma unroll 8
    for (int c = 0; c < DHID; c++)
        acc += pg[c] * Wl[(size_t)c * DIN + d];
    out[(size_t)g * DIN + d] = acc + bl[d];
}

// ---------------------------------------------------------------------------
// Launch
// ---------------------------------------------------------------------------
extern "C" void kernel_launch(void* const* d_in, const int* in_sizes, int n_in,
                              void* d_out, int out_size) {
    const float* x     = (const float*)d_in[0];
    const int*   ei    = (const int*)d_in[1];     // int32 (JAX x64-disabled)
    const int*   batch = (const int*)d_in[2];
    const float* W1 = (const float*)d_in[3];
    const float* b1 = (const float*)d_in[4];
    const float* W2 = (const float*)d_in[5];
    const float* b2 = (const float*)d_in[6];
    const float* W3 = (const float*)d_in[7];
    const float* b3 = (const float*)d_in[8];
    const float* Wl = (const float*)d_in[9];
    const float* bl = (const float*)d_in[10];
    float* out = (float*)d_out;

    const int n = in_sizes[0] / DIN;       // 50000
    const int E = in_sizes[1] / 2;         // 800000
    const int* src = ei;
    const int* dst = ei + E;

    dim3 gemm_grid(DHID / TBN, (n + TBM - 1) / TBM);     // (2, 391)
    const int agg_grid = (n * 32 + 255) / 256;
    const int nb = (n + 1023) / 1024;                    // scan blocks

    // --- CSR build + normalization ---
    init_kernel<<<(n + 256) / 256, 256>>>(n);
    hist_kernel<<<(E + 255) / 256, 256>>>(dst, E);
    dinv_kernel<<<(n + 255) / 256, 256>>>(n);
    scan1_kernel<<<nb, 1024>>>(n);
    scan2_kernel<<<1, MAXB>>>(nb, n);
    scan3_kernel<<<nb, 1024>>>(n);
    scatter_kernel<<<(E + 255) / 256, 256>>>(src, dst, E);
    gmin_kernel<<<(n + 255) / 256, 256>>>(batch, n);
    gfix_kernel<<<1, 32>>>(n);

    // --- layer 1 ---
    gemm_tc_kernel<<<gemm_grid, 256>>>(x, 1, W1, n, DIN, DHID);
    node_agg_kernel<<<agg_grid, 256>>>((const float4*)b1, n, 1);

    // --- layer 2 ---
    gemm_tc_kernel<<<gemm_grid, 256>>>(x, 0, W2, n, DHID, DHID);
    node_agg_kernel<<<agg_grid, 256>>>((const float4*)b2, n, 1);

    // --- layer 3 (no relu) ---
    gemm_tc_kernel<<<gemm_grid, 256>>>(x, 0, W3, n, DHID, DHID);
    node_agg_kernel<<<agg_grid, 256>>>((const float4*)b3, n, 0);

    // --- mean pool + head ---
    pool_kernel<<<NGRAPHS, DHID>>>();
    dim3 fgrid(DIN / 256, NGRAPHS);
    final_kernel<<<fgrid, 256>>>(Wl, bl, out);
}

// round 11
// speedup vs baseline: 2.3034x; 1.0882x over previous
#include <cuda_runtime.h>
#include <cuda_bf16.h>
#include <math.h>
#include <stdint.h>

// ---------------------------------------------------------------------------
// Problem constants
// ---------------------------------------------------------------------------
#define MAX_NODES 50000
#define MAX_EDGES 800000
#define DHID      256
#define DH4       64
#define NGRAPHS   64
#define DIN       768
#define MAXB      64

// ---------------------------------------------------------------------------
// Scratch (static device globals)
// ---------------------------------------------------------------------------
__device__ __align__(16) float g_h   [MAX_NODES * DHID];
__device__ __align__(16) float g_agg [MAX_NODES * DHID];
__device__ float g_dinv[MAX_NODES];
__device__ int   g_edeg[MAX_NODES];
__device__ int   g_off [MAX_NODES + 1];
__device__ int   g_cur [MAX_NODES];
__device__ int   g_csr [MAX_EDGES];
__device__ float g_pool[NGRAPHS * DHID];
__device__ int   g_gstart[NGRAPHS + 1];
__device__ int   g_bsum[MAXB];
__device__ int   g_bofs[MAXB];

// ---------------------------------------------------------------------------
// CSR build helpers
// ---------------------------------------------------------------------------
__global__ void init_kernel(int n) {
    int i = blockIdx.x * blockDim.x + threadIdx.x;
    if (i < n) { g_edeg[i] = 0; g_cur[i] = 0; }
    if (i <= NGRAPHS) g_gstart[i] = n;
    if (i < NGRAPHS * DHID) g_pool[i] = 0.f;
}

__global__ void hist_kernel(const int* __restrict__ dst, int E) {
    int i = blockIdx.x * blockDim.x + threadIdx.x;
    if (i < E) atomicAdd(&g_edeg[dst[i]], 1);
}

__global__ void dinv_kernel(int n) {
    int i = blockIdx.x * blockDim.x + threadIdx.x;
    if (i < n) g_dinv[i] = rsqrtf((float)(g_edeg[i] + 1));
}

__global__ __launch_bounds__(1024)
void scan1_kernel(int n) {
    __shared__ int ws[32];
    const int tid = threadIdx.x;
    const int b = blockIdx.x;
    const int i = b * 1024 + tid;
    int v = (i < n) ? g_edeg[i] : 0;
    int x = v;
    #pragma unroll
    for (int ofs = 1; ofs < 32; ofs <<= 1) {
        int y = __shfl_up_sync(0xFFFFFFFFu, x, ofs);
        if ((tid & 31) >= ofs) x += y;
    }
    if ((tid & 31) == 31) ws[tid >> 5] = x;
    __syncthreads();
    if (tid < 32) {
        int w = ws[tid];
        #pragma unroll
        for (int ofs = 1; ofs < 32; ofs <<= 1) {
            int y = __shfl_up_sync(0xFFFFFFFFu, w, ofs);
            if (tid >= ofs) w += y;
        }
        ws[tid] = w;
    }
    __syncthreads();
    int incl = x + ((tid >= 32) ? ws[(tid >> 5) - 1] : 0);
    if (i < n) g_off[i] = incl - v;
    if (tid == 1023) g_bsum[b] = incl;
}

__global__ void scan2_kernel(int nb, int n) {
    if (threadIdx.x == 0) {
        int run = 0;
        for (int b = 0; b < nb; b++) { g_bofs[b] = run; run += g_bsum[b]; }
        g_off[n] = run;
    }
}

__global__ __launch_bounds__(1024)
void scan3_kernel(int n) {
    int i = blockIdx.x * blockDim.x + threadIdx.x;
    if (i < n) g_off[i] += g_bofs[i >> 10];
}

__global__ void scatter_kernel(const int* __restrict__ src,
                               const int* __restrict__ dst, int E) {
    int i = blockIdx.x * blockDim.x + threadIdx.x;
    if (i < E) {
        int d = dst[i];
        int pos = g_off[d] + atomicAdd(&g_cur[d], 1);
        g_csr[pos] = src[i];
    }
}

__global__ void gmin_kernel(const int* __restrict__ batch, int n) {
    int i = blockIdx.x * blockDim.x + threadIdx.x;
    if (i < n) atomicMin(&g_gstart[batch[i]], i);
}

__global__ void gfix_kernel(int n) {
    if (threadIdx.x == 0 && blockIdx.x == 0) {
        g_gstart[NGRAPHS] = n;
        for (int g = NGRAPHS - 1; g >= 0; g--)
            if (g_gstart[g] > g_gstart[g + 1]) g_gstart[g] = g_gstart[g + 1];
    }
}

// ---------------------------------------------------------------------------
// tf32 tensor-core GEMM with double-buffered smem + register prefetch.
// g_h = A @ B.  CTA tile 128x128x32, 8 warps, warp tile 32x64 (m16n8k8).
// ---------------------------------------------------------------------------
#define TBM 128
#define TBN 128
#define TBK 32
#define APAD 4
#define BPAD 4

__device__ __forceinline__ uint32_t f2tf32(float f) {
    uint32_t u;
    asm("cvt.rna.tf32.f32 %0, %1;" : "=r"(u) : "f"(f));
    return u;
}

__device__ __forceinline__ void mma_tf32(float* c, const uint32_t* a, const uint32_t* b) {
    asm volatile(
        "mma.sync.aligned.m16n8k8.row.col.f32.tf32.tf32.f32 "
        "{%0,%1,%2,%3}, {%4,%5,%6,%7}, {%8,%9}, {%0,%1,%2,%3};"
        : "+f"(c[0]), "+f"(c[1]), "+f"(c[2]), "+f"(c[3])
        : "r"(a[0]), "r"(a[1]), "r"(a[2]), "r"(a[3]), "r"(b[0]), "r"(b[1]));
}

__global__ __launch_bounds__(256)
void gemm_tc_kernel(const float* __restrict__ Aext, int use_ext,
                    const float* __restrict__ B, int M, int K, int N) {
    const float* __restrict__ A = use_ext ? Aext : (const float*)g_agg;
    float* __restrict__ C = g_h;

    __shared__ float As[2][TBM][TBK + APAD];
    __shared__ float Bs[2][TBK][TBN + BPAD];

    const int tid  = threadIdx.x;
    const int warp = tid >> 5;
    const int lane = tid & 31;
    const int g    = lane >> 2;
    const int t    = lane & 3;
    const int wm   = warp >> 1;
    const int wn   = warp & 1;
    const int row0 = blockIdx.y * TBM;
    const int col0 = blockIdx.x * TBN;
    const int mbase = wm * 32;
    const int nbase = wn * 64;

    // per-thread load coords
    const int ar  = tid >> 3;          // A rows: tid/8 (+64 for second half)
    const int ac4 = tid & 7;
    const int br  = tid >> 5;          // B rows: tid/32 (+8,16,24)
    const int bc4 = tid & 31;

    float acc[2][8][4];
    #pragma unroll
    for (int mi = 0; mi < 2; mi++)
        #pragma unroll
        for (int ni = 0; ni < 8; ni++)
            #pragma unroll
            for (int r = 0; r < 4; r++) acc[mi][ni][r] = 0.f;

    // ---- prologue: load tile 0 straight to smem buf 0 ----
    {
        #pragma unroll
        for (int l = 0; l < 4; l++) {
            int r  = ar + (l >> 1) * 64;          // l=0,1 -> +0 ; l=2,3 -> +64
            int c4 = ac4;
            int f4 = tid + l * 256;
            r = f4 >> 3; c4 = f4 & 7;
            int gr = row0 + r;
            float4 v = make_float4(0.f, 0.f, 0.f, 0.f);
            if (gr < M) v = *(const float4*)&A[(size_t)gr * K + c4 * 4];
            uint4 u;
            u.x = f2tf32(v.x); u.y = f2tf32(v.y); u.z = f2tf32(v.z); u.w = f2tf32(v.w);
            *(uint4*)&As[0][r][c4 * 4] = u;
        }
        #pragma unroll
        for (int l = 0; l < 4; l++) {
            int f4 = tid + l * 256;
            int r = f4 >> 5, c4 = f4 & 31;
            float4 v = *(const float4*)&B[(size_t)r * N + col0 + c4 * 4];
            uint4 u;
            u.x = f2tf32(v.x); u.y = f2tf32(v.y); u.z = f2tf32(v.z); u.w = f2tf32(v.w);
            *(uint4*)&Bs[0][r][c4 * 4] = u;
        }
    }
    __syncthreads();

    int buf = 0;
    for (int k0 = 0; k0 < K; k0 += TBK) {
        const int kn = k0 + TBK;
        const bool has_next = kn < K;

        // ---- issue next-tile global loads into registers ----
        float4 pa[4], pb[4];
        if (has_next) {
            #pragma unroll
            for (int l = 0; l < 4; l++) {
                int f4 = tid + l * 256;
                int r = f4 >> 3, c4 = f4 & 7;
                int gr = row0 + r;
                pa[l] = make_float4(0.f, 0.f, 0.f, 0.f);
                if (gr < M) pa[l] = *(const float4*)&A[(size_t)gr * K + kn + c4 * 4];
            }
            #pragma unroll
            for (int l = 0; l < 4; l++) {
                int f4 = tid + l * 256;
                int r = f4 >> 5, c4 = f4 & 31;
                pb[l] = *(const float4*)&B[(size_t)(kn + r) * N + col0 + c4 * 4];
            }
        }

        // ---- compute current buffer ----
        #pragma unroll
        for (int k8 = 0; k8 < TBK / 8; k8++) {
            const int kk = k8 * 8;
            uint32_t a[2][4];
            #pragma unroll
            for (int mi = 0; mi < 2; mi++) {
                int r = mbase + mi * 16;
                a[mi][0] = __float_as_uint(As[buf][r + g    ][kk + t    ]);
                a[mi][1] = __float_as_uint(As[buf][r + g + 8][kk + t    ]);
                a[mi][2] = __float_as_uint(As[buf][r + g    ][kk + t + 4]);
                a[mi][3] = __float_as_uint(As[buf][r + g + 8][kk + t + 4]);
            }
            uint32_t b[8][2];
            #pragma unroll
            for (int ni = 0; ni < 8; ni++) {
                int c = nbase + ni * 8 + g;
                b[ni][0] = __float_as_uint(Bs[buf][kk + t    ][c]);
                b[ni][1] = __float_as_uint(Bs[buf][kk + t + 4][c]);
            }
            #pragma unroll
            for (int mi = 0; mi < 2; mi++)
                #pragma unroll
                for (int ni = 0; ni < 8; ni++)
                    mma_tf32(acc[mi][ni], a[mi], b[ni]);
        }

        // ---- convert + store next tile ----
        if (has_next) {
            int nb_ = buf ^ 1;
            #pragma unroll
            for (int l = 0; l < 4; l++) {
                int f4 = tid + l * 256;
                int r = f4 >> 3, c4 = f4 & 7;
                uint4 u;
                u.x = f2tf32(pa[l].x); u.y = f2tf32(pa[l].y);
                u.z = f2tf32(pa[l].z); u.w = f2tf32(pa[l].w);
                *(uint4*)&As[nb_][r][c4 * 4] = u;
            }
            #pragma unroll
            for (int l = 0; l < 4; l++) {
                int f4 = tid + l * 256;
                int r = f4 >> 5, c4 = f4 & 31;
                uint4 u;
                u.x = f2tf32(pb[l].x); u.y = f2tf32(pb[l].y);
                u.z = f2tf32(pb[l].z); u.w = f2tf32(pb[l].w);
                *(uint4*)&Bs[nb_][r][c4 * 4] = u;
            }
        }
        __syncthreads();
        buf ^= 1;
    }

    #pragma unroll
    for (int mi = 0; mi < 2; mi++) {
        int r_lo = row0 + mbase + mi * 16 + g;
        int r_hi = r_lo + 8;
        #pragma unroll
        for (int ni = 0; ni < 8; ni++) {
            int c = col0 + nbase + ni * 8 + 2 * t;
            if (r_lo < M) *(float2*)&C[(size_t)r_lo * N + c] =
                make_float2(acc[mi][ni][0], acc[mi][ni][1]);
            if (r_hi < M) *(float2*)&C[(size_t)r_hi * N + c] =
                make_float2(acc[mi][ni][2], acc[mi][ni][3]);
        }
    }
}

// ---------------------------------------------------------------------------
// Fused aggregation: warp per node, atomic-free, 2-edge unroll for MLP
// ---------------------------------------------------------------------------
__global__ __launch_bounds__(256)
void node_agg_kernel(const float4* __restrict__ bias, int n, int do_relu) {
    int node = (blockIdx.x * blockDim.x + threadIdx.x) >> 5;
    if (node >= n) return;
    int lane = threadIdx.x & 31;

    const float4* __restrict__ h4 = (const float4*)g_h;
    const int beg = g_off[node];
    const int end = g_off[node + 1];
    const float dn = g_dinv[node];

    float4 a0 = make_float4(0.f, 0.f, 0.f, 0.f);
    float4 a1 = make_float4(0.f, 0.f, 0.f, 0.f);

    int e = beg;
    for (; e + 2 <= end; e += 2) {
        int s0 = g_csr[e];
        int s1 = g_csr[e + 1];
        float nm0 = dn * g_dinv[s0];
        float nm1 = dn * g_dinv[s1];
        float4 v00 = h4[(size_t)s0 * DH4 + lane];
        float4 v01 = h4[(size_t)s0 * DH4 + lane + 32];
        float4 v10 = h4[(size_t)s1 * DH4 + lane];
        float4 v11 = h4[(size_t)s1 * DH4 + lane + 32];
        a0.x += v00.x * nm0; a0.y += v00.y * nm0; a0.z += v00.z * nm0; a0.w += v00.w * nm0;
        a1.x += v01.x * nm0; a1.y += v01.y * nm0; a1.z += v01.z * nm0; a1.w += v01.w * nm0;
        a0.x += v10.x * nm1; a0.y += v10.y * nm1; a0.z += v10.z * nm1; a0.w += v10.w * nm1;
        a1.x += v11.x * nm1; a1.y += v11.y * nm1; a1.z += v11.z * nm1; a1.w += v11.w * nm1;
    }
    if (e < end) {
        int s = g_csr[e];
        float nm = dn * g_dinv[s];
        float4 v0 = h4[(size_t)s * DH4 + lane];
        float4 v1 = h4[(size_t)s * DH4 + lane + 32];
        a0.x += v0.x * nm; a0.y += v0.y * nm; a0.z += v0.z * nm; a0.w += v0.w * nm;
        a1.x += v1.x * nm; a1.y += v1.y * nm; a1.z += v1.z * nm; a1.w += v1.w * nm;
    }

    float sl = dn * dn;
    float4 s0 = h4[(size_t)node * DH4 + lane];
    float4 s1 = h4[(size_t)node * DH4 + lane + 32];
    float4 b0 = bias[lane];
    float4 b1 = bias[lane + 32];
    a0.x += s0.x * sl + b0.x; a0.y += s0.y * sl + b0.y;
    a0.z += s0.z * sl + b0.z; a0.w += s0.w * sl + b0.w;
    a1.x += s1.x * sl + b1.x; a1.y += s1.y * sl + b1.y;
    a1.z += s1.z * sl + b1.z; a1.w += s1.w * sl + b1.w;

    if (do_relu) {
        a0.x = fmaxf(a0.x, 0.f); a0.y = fmaxf(a0.y, 0.f);
        a0.z = fmaxf(a0.z, 0.f); a0.w = fmaxf(a0.w, 0.f);
        a1.x = fmaxf(a1.x, 0.f); a1.y = fmaxf(a1.y, 0.f);
        a1.z = fmaxf(a1.z, 0.f); a1.w = fmaxf(a1.w, 0.f);
    }

    float4* agg4 = (float4*)g_agg;
    agg4[(size_t)node * DH4 + lane]      = a0;
    agg4[(size_t)node * DH4 + lane + 32] = a1;
}

// ---------------------------------------------------------------------------
// Mean pool: 4 CTAs per graph, partial sums via atomicAdd (pool pre-zeroed)
// ---------------------------------------------------------------------------
#define POOL_SPLIT 4

__global__ __launch_bounds__(DHID)
void pool_kernel() {
    int g = blockIdx.x >> 2;           // graph
    int p = blockIdx.x & 3;            // partition
    int c = threadIdx.x;
    int beg = g_gstart[g], end = g_gstart[g + 1];
    int len = end - beg;
    int chunk = (len + POOL_SPLIT - 1) / POOL_SPLIT;
    int lo = beg + p * chunk;
    int hi = min(lo + chunk, end);
    if (lo >= hi) return;
    float acc = 0.f;
    int i = lo;
    for (; i + 4 <= hi; i += 4) {
        acc += g_agg[(size_t)(i + 0) * DHID + c];
        acc += g_agg[(size_t)(i + 1) * DHID + c];
        acc += g_agg[(size_t)(i + 2) * DHID + c];
        acc += g_agg[(size_t)(i + 3) * DHID + c];
    }
    for (; i < hi; i++) acc += g_agg[(size_t)i * DHID + c];
    atomicAdd(&g_pool[g * DHID + c], acc);
}

// ---------------------------------------------------------------------------
// Final linear (mean division folded in): out = (sum @ Wl)/cnt + bl
// ---------------------------------------------------------------------------
__global__ __launch_bounds__(256)
void final_kernel(const float* __restrict__ Wl, const float* __restrict__ bl,
                  float* __restrict__ out) {
    int d = blockIdx.x * blockDim.x + threadIdx.x;
    int g = blockIdx.y;
    const float* pg = g_pool + g * DHID;
    float acc = 0.f;
    #pragma unroll 8
    for (int c = 0; c < DHID; c++)
        acc += pg[c] * Wl[(size_t)c * DIN + d];
    float cnt = (float)(g_gstart[g + 1] - g_gstart[g]);
    out[(size_t)g * DIN + d] = acc / fmaxf(cnt, 1.f) + bl[d];
}

// ---------------------------------------------------------------------------
// Launch.  Layer-1 GEMM is the 4th launch so ncu profiles it.
// ---------------------------------------------------------------------------
extern "C" void kernel_launch(void* const* d_in, const int* in_sizes, int n_in,
                              void* d_out, int out_size) {
    const float* x     = (const float*)d_in[0];
    const int*   ei    = (const int*)d_in[1];
    const int*   batch = (const int*)d_in[2];
    const float* W1 = (const float*)d_in[3];
    const float* b1 = (const float*)d_in[4];
    const float* W2 = (const float*)d_in[5];
    const float* b2 = (const float*)d_in[6];
    const float* W3 = (const float*)d_in[7];
    const float* b3 = (const float*)d_in[8];
    const float* Wl = (const float*)d_in[9];
    const float* bl = (const float*)d_in[10];
    float* out = (float*)d_out;

    const int n = in_sizes[0] / DIN;       // 50000
    const int E = in_sizes[1] / 2;         // 800000
    const int* src = ei;
    const int* dst = ei + E;

    dim3 gemm_grid(DHID / TBN, (n + TBM - 1) / TBM);
    const int agg_grid = (n * 32 + 255) / 256;
    const int nb = (n + 1023) / 1024;

    // launches 1-3
    init_kernel<<<(n + 256) / 256, 256>>>(n);
    hist_kernel<<<(E + 255) / 256, 256>>>(dst, E);
    dinv_kernel<<<(n + 255) / 256, 256>>>(n);

    // launch 4: layer-1 GEMM (profiled by ncu; independent of CSR)
    gemm_tc_kernel<<<gemm_grid, 256>>>(x, 1, W1, n, DIN, DHID);

    // CSR build (overlaps conceptually; stream-ordered after gemm)
    scan1_kernel<<<nb, 1024>>>(n);
    scan2_kernel<<<1, 32>>>(nb, n);
    scan3_kernel<<<nb, 1024>>>(n);
    scatter_kernel<<<(E + 255) / 256, 256>>>(src, dst, E);
    gmin_kernel<<<(n + 255) / 256, 256>>>(batch, n);
    gfix_kernel<<<1, 32>>>(n);

    // layer 1 aggregation
    node_agg_kernel<<<agg_grid, 256>>>((const float4*)b1, n, 1);

    // layer 2
    gemm_tc_kernel<<<gemm_grid, 256>>>(x, 0, W2, n, DHID, DHID);
    node_agg_kernel<<<agg_grid, 256>>>((const float4*)b2, n, 1);

    // layer 3 (no relu)
    gemm_tc_kernel<<<gemm_grid, 256>>>(x, 0, W3, n, DHID, DHID);
    node_agg_kernel<<<agg_grid, 256>>>((const float4*)b3, n, 0);

    // mean pool + head
    pool_kernel<<<NGRAPHS * POOL_SPLIT, DHID>>>();
    dim3 fgrid(DIN / 256, NGRAPHS);
    final_kernel<<<fgrid, 256>>>(Wl, bl, out);
}

// round 12
// speedup vs baseline: 2.9439x; 1.2780x over previous
#include <cuda_runtime.h>
#include <cuda_fp16.h>
#include <math.h>
#include <stdint.h>

// ---------------------------------------------------------------------------
// Problem constants
// ---------------------------------------------------------------------------
#define MAX_NODES 50000
#define MAX_EDGES 800000
#define DHID      256
#define DH4       64
#define NGRAPHS   64
#define DIN       768
#define MAXB      64

// ---------------------------------------------------------------------------
// Scratch (static device globals)
// ---------------------------------------------------------------------------
__device__ __align__(16) float g_h   [MAX_NODES * DHID];
__device__ __align__(16) float g_agg [MAX_NODES * DHID];
__device__ float g_dinv[MAX_NODES];
__device__ int   g_edeg[MAX_NODES];
__device__ int   g_off [MAX_NODES + 1];
__device__ int   g_cur [MAX_NODES];
__device__ int   g_csr [MAX_EDGES];
__device__ float g_pool[NGRAPHS * DHID];
__device__ int   g_gstart[NGRAPHS + 1];
__device__ int   g_bsum[MAXB];
__device__ int   g_bofs[MAXB];

// ---------------------------------------------------------------------------
// CSR build helpers
// ---------------------------------------------------------------------------
__global__ void init_kernel(int n) {
    int i = blockIdx.x * blockDim.x + threadIdx.x;
    if (i < n) { g_edeg[i] = 0; g_cur[i] = 0; }
    if (i <= NGRAPHS) g_gstart[i] = n;
    if (i < NGRAPHS * DHID) g_pool[i] = 0.f;
}

__global__ void hist_kernel(const int* __restrict__ dst, int E) {
    int i = blockIdx.x * blockDim.x + threadIdx.x;
    if (i < E) atomicAdd(&g_edeg[dst[i]], 1);
}

__global__ void dinv_kernel(int n) {
    int i = blockIdx.x * blockDim.x + threadIdx.x;
    if (i < n) g_dinv[i] = rsqrtf((float)(g_edeg[i] + 1));
}

__global__ __launch_bounds__(1024)
void scan1_kernel(int n) {
    __shared__ int ws[32];
    const int tid = threadIdx.x;
    const int b = blockIdx.x;
    const int i = b * 1024 + tid;
    int v = (i < n) ? g_edeg[i] : 0;
    int x = v;
    #pragma unroll
    for (int ofs = 1; ofs < 32; ofs <<= 1) {
        int y = __shfl_up_sync(0xFFFFFFFFu, x, ofs);
        if ((tid & 31) >= ofs) x += y;
    }
    if ((tid & 31) == 31) ws[tid >> 5] = x;
    __syncthreads();
    if (tid < 32) {
        int w = ws[tid];
        #pragma unroll
        for (int ofs = 1; ofs < 32; ofs <<= 1) {
            int y = __shfl_up_sync(0xFFFFFFFFu, w, ofs);
            if (tid >= ofs) w += y;
        }
        ws[tid] = w;
    }
    __syncthreads();
    int incl = x + ((tid >= 32) ? ws[(tid >> 5) - 1] : 0);
    if (i < n) g_off[i] = incl - v;
    if (tid == 1023) g_bsum[b] = incl;
}

__global__ void scan2_kernel(int nb, int n) {
    if (threadIdx.x == 0) {
        int run = 0;
        for (int b = 0; b < nb; b++) { g_bofs[b] = run; run += g_bsum[b]; }
        g_off[n] = run;
    }
}

__global__ __launch_bounds__(1024)
void scan3_kernel(int n) {
    int i = blockIdx.x * blockDim.x + threadIdx.x;
    if (i < n) g_off[i] += g_bofs[i >> 10];
}

__global__ void scatter_kernel(const int* __restrict__ src,
                               const int* __restrict__ dst, int E) {
    int i = blockIdx.x * blockDim.x + threadIdx.x;
    if (i < E) {
        int d = dst[i];
        int pos = g_off[d] + atomicAdd(&g_cur[d], 1);
        g_csr[pos] = src[i];
    }
}

__global__ void gmin_kernel(const int* __restrict__ batch, int n) {
    int i = blockIdx.x * blockDim.x + threadIdx.x;
    if (i < n) atomicMin(&g_gstart[batch[i]], i);
}

__global__ void gfix_kernel(int n) {
    if (threadIdx.x == 0 && blockIdx.x == 0) {
        g_gstart[NGRAPHS] = n;
        for (int g = NGRAPHS - 1; g >= 0; g--)
            if (g_gstart[g] > g_gstart[g + 1]) g_gstart[g] = g_gstart[g + 1];
    }
}

// ---------------------------------------------------------------------------
// fp16 tensor-core GEMM (fp32 accumulate): g_h = A @ B.
// CTA tile 128x128x32, 8 warps, warp tile 32x64 via m16n8k16.
// Fragments loaded with ldmatrix (A row-major, B k-major via .trans).
// ---------------------------------------------------------------------------
#define TBM 128
#define TBN 128
#define TBK 32
#define APADH 8     // Ah row = 40 half = 80 B (16B mult, conflict-free ldsm)
#define BPADH 8     // Bh row = 136 half = 272 B

#define AROW (TBK + APADH)
#define BROW (TBN + BPADH)

__device__ __forceinline__ void ldsm_x4(uint32_t& r0, uint32_t& r1,
                                        uint32_t& r2, uint32_t& r3, uint32_t addr) {
    asm volatile("ldmatrix.sync.aligned.m8n8.x4.shared.b16 {%0,%1,%2,%3}, [%4];"
                 : "=r"(r0), "=r"(r1), "=r"(r2), "=r"(r3) : "r"(addr));
}

__device__ __forceinline__ void ldsm_x4_t(uint32_t& r0, uint32_t& r1,
                                          uint32_t& r2, uint32_t& r3, uint32_t addr) {
    asm volatile("ldmatrix.sync.aligned.m8n8.x4.trans.shared.b16 {%0,%1,%2,%3}, [%4];"
                 : "=r"(r0), "=r"(r1), "=r"(r2), "=r"(r3) : "r"(addr));
}

__device__ __forceinline__ void mma_f16(float* c, const uint32_t* a, const uint32_t* b) {
    asm volatile(
        "mma.sync.aligned.m16n8k16.row.col.f32.f16.f16.f32 "
        "{%0,%1,%2,%3}, {%4,%5,%6,%7}, {%8,%9}, {%0,%1,%2,%3};"
        : "+f"(c[0]), "+f"(c[1]), "+f"(c[2]), "+f"(c[3])
        : "r"(a[0]), "r"(a[1]), "r"(a[2]), "r"(a[3]), "r"(b[0]), "r"(b[1]));
}

__device__ __forceinline__ uint2 pack4h(float4 v) {
    __half2 h0 = __floats2half2_rn(v.x, v.y);
    __half2 h1 = __floats2half2_rn(v.z, v.w);
    uint2 u;
    u.x = *(uint32_t*)&h0;
    u.y = *(uint32_t*)&h1;
    return u;
}

__global__ __launch_bounds__(256)
void gemm_tc_kernel(const float* __restrict__ Aext, int use_ext,
                    const float* __restrict__ B, int M, int K, int N) {
    const float* __restrict__ A = use_ext ? Aext : (const float*)g_agg;
    float* __restrict__ C = g_h;

    __shared__ __align__(16) __half Ah[2][TBM][AROW];
    __shared__ __align__(16) __half Bh[2][TBK][BROW];

    const int tid  = threadIdx.x;
    const int warp = tid >> 5;
    const int lane = tid & 31;
    const int g    = lane >> 2;
    const int t    = lane & 3;
    const int wm   = warp >> 1;
    const int wn   = warp & 1;
    const int row0 = blockIdx.y * TBM;
    const int col0 = blockIdx.x * TBN;
    const int mbase = wm * 32;
    const int nbase = wn * 64;

    // ldmatrix per-lane address components (shared by A and B patterns)
    const int lquad = lane & 15;          // row offset within 16
    const int lhalf = (lane >> 4) << 3;   // 0 or 8 (column 16B group)

    const uint32_t a_smem0 = (uint32_t)__cvta_generic_to_shared(&Ah[0][0][0]);
    const uint32_t b_smem0 = (uint32_t)__cvta_generic_to_shared(&Bh[0][0][0]);
    const uint32_t a_buf_sz = TBM * AROW * 2;   // bytes per buffer
    const uint32_t b_buf_sz = TBK * BROW * 2;

    float acc[2][8][4];
    #pragma unroll
    for (int mi = 0; mi < 2; mi++)
        #pragma unroll
        for (int ni = 0; ni < 8; ni++)
            #pragma unroll
            for (int r = 0; r < 4; r++) acc[mi][ni][r] = 0.f;

    // ---- prologue: tile 0 -> buf 0 ----
    {
        #pragma unroll
        for (int l = 0; l < 4; l++) {
            int p  = tid + l * 256;
            int r  = p >> 3, c4 = p & 7;
            int gr = row0 + r;
            float4 v = make_float4(0.f, 0.f, 0.f, 0.f);
            if (gr < M) v = *(const float4*)&A[(size_t)gr * K + c4 * 4];
            *(uint2*)&Ah[0][r][c4 * 4] = pack4h(v);
        }
        #pragma unroll
        for (int l = 0; l < 4; l++) {
            int p = tid + l * 256;
            int r = p >> 5, c4 = p & 31;
            float4 v = *(const float4*)&B[(size_t)r * N + col0 + c4 * 4];
            *(uint2*)&Bh[0][r][c4 * 4] = pack4h(v);
        }
    }
    __syncthreads();

    int buf = 0;
    for (int k0 = 0; k0 < K; k0 += TBK) {
        const int kn = k0 + TBK;
        const bool has_next = kn < K;

        // ---- prefetch next tile into registers ----
        float4 pa[4], pb[4];
        if (has_next) {
            #pragma unroll
            for (int l = 0; l < 4; l++) {
                int p = tid + l * 256;
                int r = p >> 3, c4 = p & 7;
                int gr = row0 + r;
                pa[l] = make_float4(0.f, 0.f, 0.f, 0.f);
                if (gr < M) pa[l] = *(const float4*)&A[(size_t)gr * K + kn + c4 * 4];
            }
            #pragma unroll
            for (int l = 0; l < 4; l++) {
                int p = tid + l * 256;
                int r = p >> 5, c4 = p & 31;
                pb[l] = *(const float4*)&B[(size_t)(kn + r) * N + col0 + c4 * 4];
            }
        }

        // ---- compute current buffer: 2 x k16 ----
        const uint32_t a_base = a_smem0 + buf * a_buf_sz;
        const uint32_t b_base = b_smem0 + buf * b_buf_sz;
        #pragma unroll
        for (int k16 = 0; k16 < 2; k16++) {
            const int kk = k16 * 16;
            uint32_t a[2][4];
            #pragma unroll
            for (int mi = 0; mi < 2; mi++) {
                uint32_t addr = a_base +
                    ((mbase + mi * 16 + lquad) * AROW + kk + lhalf) * 2;
                ldsm_x4(a[mi][0], a[mi][1], a[mi][2], a[mi][3], addr);
            }
            uint32_t b[8][2];
            #pragma unroll
            for (int pr = 0; pr < 4; pr++) {      // pairs of ni
                uint32_t addr = b_base +
                    ((kk + lquad) * BROW + nbase + pr * 16 + lhalf) * 2;
                ldsm_x4_t(b[pr * 2][0], b[pr * 2][1],
                          b[pr * 2 + 1][0], b[pr * 2 + 1][1], addr);
            }
            #pragma unroll
            for (int mi = 0; mi < 2; mi++)
                #pragma unroll
                for (int ni = 0; ni < 8; ni++)
                    mma_f16(acc[mi][ni], a[mi], b[ni]);
        }

        // ---- convert + store next tile ----
        if (has_next) {
            int nb_ = buf ^ 1;
            #pragma unroll
            for (int l = 0; l < 4; l++) {
                int p = tid + l * 256;
                int r = p >> 3, c4 = p & 7;
                *(uint2*)&Ah[nb_][r][c4 * 4] = pack4h(pa[l]);
            }
            #pragma unroll
            for (int l = 0; l < 4; l++) {
                int p = tid + l * 256;
                int r = p >> 5, c4 = p & 31;
                *(uint2*)&Bh[nb_][r][c4 * 4] = pack4h(pb[l]);
            }
        }
        __syncthreads();
        buf ^= 1;
    }

    #pragma unroll
    for (int mi = 0; mi < 2; mi++) {
        int r_lo = row0 + mbase + mi * 16 + g;
        int r_hi = r_lo + 8;
        #pragma unroll
        for (int ni = 0; ni < 8; ni++) {
            int c = col0 + nbase + ni * 8 + 2 * t;
            if (r_lo < M) *(float2*)&C[(size_t)r_lo * N + c] =
                make_float2(acc[mi][ni][0], acc[mi][ni][1]);
            if (r_hi < M) *(float2*)&C[(size_t)r_hi * N + c] =
                make_float2(acc[mi][ni][2], acc[mi][ni][3]);
        }
    }
}

// ---------------------------------------------------------------------------
// Fused aggregation: warp per node, atomic-free, 2-edge unroll
// ---------------------------------------------------------------------------
__global__ __launch_bounds__(256)
void node_agg_kernel(const float4* __restrict__ bias, int n, int do_relu) {
    int node = (blockIdx.x * blockDim.x + threadIdx.x) >> 5;
    if (node >= n) return;
    int lane = threadIdx.x & 31;

    const float4* __restrict__ h4 = (const float4*)g_h;
    const int beg = g_off[node];
    const int end = g_off[node + 1];
    const float dn = g_dinv[node];

    float4 a0 = make_float4(0.f, 0.f, 0.f, 0.f);
    float4 a1 = make_float4(0.f, 0.f, 0.f, 0.f);

    int e = beg;
    for (; e + 2 <= end; e += 2) {
        int s0 = g_csr[e];
        int s1 = g_csr[e + 1];
        float nm0 = dn * g_dinv[s0];
        float nm1 = dn * g_dinv[s1];
        float4 v00 = h4[(size_t)s0 * DH4 + lane];
        float4 v01 = h4[(size_t)s0 * DH4 + lane + 32];
        float4 v10 = h4[(size_t)s1 * DH4 + lane];
        float4 v11 = h4[(size_t)s1 * DH4 + lane + 32];
        a0.x += v00.x * nm0; a0.y += v00.y * nm0; a0.z += v00.z * nm0; a0.w += v00.w * nm0;
        a1.x += v01.x * nm0; a1.y += v01.y * nm0; a1.z += v01.z * nm0; a1.w += v01.w * nm0;
        a0.x += v10.x * nm1; a0.y += v10.y * nm1; a0.z += v10.z * nm1; a0.w += v10.w * nm1;
        a1.x += v11.x * nm1; a1.y += v11.y * nm1; a1.z += v11.z * nm1; a1.w += v11.w * nm1;
    }
    if (e < end) {
        int s = g_csr[e];
        float nm = dn * g_dinv[s];
        float4 v0 = h4[(size_t)s * DH4 + lane];
        float4 v1 = h4[(size_t)s * DH4 + lane + 32];
        a0.x += v0.x * nm; a0.y += v0.y * nm; a0.z += v0.z * nm; a0.w += v0.w * nm;
        a1.x += v1.x * nm; a1.y += v1.y * nm; a1.z += v1.z * nm; a1.w += v1.w * nm;
    }

    float sl = dn * dn;
    float4 s0 = h4[(size_t)node * DH4 + lane];
    float4 s1 = h4[(size_t)node * DH4 + lane + 32];
    float4 b0 = bias[lane];
    float4 b1 = bias[lane + 32];
    a0.x += s0.x * sl + b0.x; a0.y += s0.y * sl + b0.y;
    a0.z += s0.z * sl + b0.z; a0.w += s0.w * sl + b0.w;
    a1.x += s1.x * sl + b1.x; a1.y += s1.y * sl + b1.y;
    a1.z += s1.z * sl + b1.z; a1.w += s1.w * sl + b1.w;

    if (do_relu) {
        a0.x = fmaxf(a0.x, 0.f); a0.y = fmaxf(a0.y, 0.f);
        a0.z = fmaxf(a0.z, 0.f); a0.w = fmaxf(a0.w, 0.f);
        a1.x = fmaxf(a1.x, 0.f); a1.y = fmaxf(a1.y, 0.f);
        a1.z = fmaxf(a1.z, 0.f); a1.w = fmaxf(a1.w, 0.f);
    }

    float4* agg4 = (float4*)g_agg;
    agg4[(size_t)node * DH4 + lane]      = a0;
    agg4[(size_t)node * DH4 + lane + 32] = a1;
}

// ---------------------------------------------------------------------------
// Mean pool: 4 CTAs per graph, partial sums via atomicAdd (pool pre-zeroed)
// ---------------------------------------------------------------------------
#define POOL_SPLIT 4

__global__ __launch_bounds__(DHID)
void pool_kernel() {
    int g = blockIdx.x >> 2;
    int p = blockIdx.x & 3;
    int c = threadIdx.x;
    int beg = g_gstart[g], end = g_gstart[g + 1];
    int len = end - beg;
    int chunk = (len + POOL_SPLIT - 1) / POOL_SPLIT;
    int lo = beg + p * chunk;
    int hi = min(lo + chunk, end);
    if (lo >= hi) return;
    float acc = 0.f;
    int i = lo;
    for (; i + 4 <= hi; i += 4) {
        acc += g_agg[(size_t)(i + 0) * DHID + c];
        acc += g_agg[(size_t)(i + 1) * DHID + c];
        acc += g_agg[(size_t)(i + 2) * DHID + c];
        acc += g_agg[(size_t)(i + 3) * DHID + c];
    }
    for (; i < hi; i++) acc += g_agg[(size_t)i * DHID + c];
    atomicAdd(&g_pool[g * DHID + c], acc);
}

// ---------------------------------------------------------------------------
// Final linear (mean division folded in)
// ---------------------------------------------------------------------------
__global__ __launch_bounds__(256)
void final_kernel(const float* __restrict__ Wl, const float* __restrict__ bl,
                  float* __restrict__ out) {
    int d = blockIdx.x * blockDim.x + threadIdx.x;
    int g = blockIdx.y;
    const float* pg = g_pool + g * DHID;
    float acc = 0.f;
    #pragma unroll 8
    for (int c = 0; c < DHID; c++)
        acc += pg[c] * Wl[(size_t)c * DIN + d];
    float cnt = (float)(g_gstart[g + 1] - g_gstart[g]);
    out[(size_t)g * DIN + d] = acc / fmaxf(cnt, 1.f) + bl[d];
}

// ---------------------------------------------------------------------------
// Launch.  Layer-1 GEMM is the 4th launch so ncu profiles it.
// ---------------------------------------------------------------------------
extern "C" void kernel_launch(void* const* d_in, const int* in_sizes, int n_in,
                              void* d_out, int out_size) {
    const float* x     = (const float*)d_in[0];
    const int*   ei    = (const int*)d_in[1];
    const int*   batch = (const int*)d_in[2];
    const float* W1 = (const float*)d_in[3];
    const float* b1 = (const float*)d_in[4];
    const float* W2 = (const float*)d_in[5];
    const float* b2 = (const float*)d_in[6];
    const float* W3 = (const float*)d_in[7];
    const float* b3 = (const float*)d_in[8];
    const float* Wl = (const float*)d_in[9];
    const float* bl = (const float*)d_in[10];
    float* out = (float*)d_out;

    const int n = in_sizes[0] / DIN;       // 50000
    const int E = in_sizes[1] / 2;         // 800000
    const int* src = ei;
    const int* dst = ei + E;

    dim3 gemm_grid(DHID / TBN, (n + TBM - 1) / TBM);
    const int agg_grid = (n * 32 + 255) / 256;
    const int nb = (n + 1023) / 1024;

    // launches 1-3
    init_kernel<<<(n + 256) / 256, 256>>>(n);
    hist_kernel<<<(E + 255) / 256, 256>>>(dst, E);
    dinv_kernel<<<(n + 255) / 256, 256>>>(n);

    // launch 4: layer-1 GEMM (profiled by ncu; independent of CSR)
    gemm_tc_kernel<<<gemm_grid, 256>>>(x, 1, W1, n, DIN, DHID);

    // CSR build
    scan1_kernel<<<nb, 1024>>>(n);
    scan2_kernel<<<1, 32>>>(nb, n);
    scan3_kernel<<<nb, 1024>>>(n);
    scatter_kernel<<<(E + 255) / 256, 256>>>(src, dst, E);
    gmin_kernel<<<(n + 255) / 256, 256>>>(batch, n);
    gfix_kernel<<<1, 32>>>(n);

    // layer 1 aggregation
    node_agg_kernel<<<agg_grid, 256>>>((const float4*)b1, n, 1);

    // layer 2
    gemm_tc_kernel<<<gemm_grid, 256>>>(x, 0, W2, n, DHID, DHID);
    node_agg_kernel<<<agg_grid, 256>>>((const float4*)b2, n, 1);

    // layer 3 (no relu)
    gemm_tc_kernel<<<gemm_grid, 256>>>(x, 0, W3, n, DHID, DHID);
    node_agg_kernel<<<agg_grid, 256>>>((const float4*)b3, n, 0);

    // mean pool + head
    pool_kernel<<<NGRAPHS * POOL_SPLIT, DHID>>>();
    dim3 fgrid(DIN / 256, NGRAPHS);
    final_kernel<<<fgrid, 256>>>(Wl, bl, out);
}

// round 13
// speedup vs baseline: 3.6532x; 1.2409x over previous
#include <cuda_runtime.h>
#include <cuda_fp16.h>
#include <math.h>
#include <stdint.h>

// ---------------------------------------------------------------------------
// Problem constants
// ---------------------------------------------------------------------------
#define MAX_NODES 50000
#define MAX_EDGES 800000
#define DHID      256
#define DH8       32          // DHID / 8 (uint4 chunks of half)
#define NGRAPHS   64
#define DIN       768
#define MAXB      64

// ---------------------------------------------------------------------------
// Scratch (static device globals)
// ---------------------------------------------------------------------------
__device__ __align__(16) __half g_hh  [MAX_NODES * DHID];  // GEMM output (fp16)
__device__ __align__(16) __half g_aggh[MAX_NODES * DHID];  // aggregated (fp16)
__device__ __align__(16) __half g_w1h [DIN * DHID];        // fp16 weights
__device__ __align__(16) __half g_w2h [DHID * DHID];
__device__ __align__(16) __half g_w3h [DHID * DHID];
__device__ float g_dinv[MAX_NODES];
__device__ int   g_edeg[MAX_NODES];
__device__ int   g_off [MAX_NODES + 1];
__device__ int   g_cur [MAX_NODES];
__device__ int   g_csr [MAX_EDGES];
__device__ float g_pool[NGRAPHS * DHID];
__device__ int   g_gstart[NGRAPHS + 1];
__device__ int   g_bsum[MAXB];
__device__ int   g_bofs[MAXB];

// ---------------------------------------------------------------------------
// init: zero histogram/cursors/pool, init gstart, convert weights to fp16.
// Grid covers DIN*DHID elements (largest task).
// ---------------------------------------------------------------------------
__global__ void init_kernel(const float* __restrict__ W1,
                            const float* __restrict__ W2,
                            const float* __restrict__ W3, int n) {
    int i = blockIdx.x * blockDim.x + threadIdx.x;
    if (i < n) { g_edeg[i] = 0; g_cur[i] = 0; }
    if (i <= NGRAPHS) g_gstart[i] = n;
    if (i < NGRAPHS * DHID) g_pool[i] = 0.f;
    if (i < DIN * DHID) g_w1h[i] = __float2half(W1[i]);
    if (i < DHID * DHID) {
        g_w2h[i] = __float2half(W2[i]);
        g_w3h[i] = __float2half(W3[i]);
    }
}

__global__ void hist_kernel(const int* __restrict__ dst, int E) {
    int i = blockIdx.x * blockDim.x + threadIdx.x;
    if (i < E) atomicAdd(&g_edeg[dst[i]], 1);
}

__global__ void dinv_kernel(int n) {
    int i = blockIdx.x * blockDim.x + threadIdx.x;
    if (i < n) g_dinv[i] = rsqrtf((float)(g_edeg[i] + 1));
}

__global__ __launch_bounds__(1024)
void scan1_kernel(int n) {
    __shared__ int ws[32];
    const int tid = threadIdx.x;
    const int b = blockIdx.x;
    const int i = b * 1024 + tid;
    int v = (i < n) ? g_edeg[i] : 0;
    int x = v;
    #pragma unroll
    for (int ofs = 1; ofs < 32; ofs <<= 1) {
        int y = __shfl_up_sync(0xFFFFFFFFu, x, ofs);
        if ((tid & 31) >= ofs) x += y;
    }
    if ((tid & 31) == 31) ws[tid >> 5] = x;
    __syncthreads();
    if (tid < 32) {
        int w = ws[tid];
        #pragma unroll
        for (int ofs = 1; ofs < 32; ofs <<= 1) {
            int y = __shfl_up_sync(0xFFFFFFFFu, w, ofs);
            if (tid >= ofs) w += y;
        }
        ws[tid] = w;
    }
    __syncthreads();
    int incl = x + ((tid >= 32) ? ws[(tid >> 5) - 1] : 0);
    if (i < n) g_off[i] = incl - v;
    if (tid == 1023) g_bsum[b] = incl;
}

__global__ void scan2_kernel(int nb, int n) {
    if (threadIdx.x == 0) {
        int run = 0;
        for (int b = 0; b < nb; b++) { g_bofs[b] = run; run += g_bsum[b]; }
        g_off[n] = run;
    }
}

__global__ __launch_bounds__(1024)
void scan3_kernel(int n) {
    int i = blockIdx.x * blockDim.x + threadIdx.x;
    if (i < n) g_off[i] += g_bofs[i >> 10];
}

__global__ void scatter_kernel(const int* __restrict__ src,
                               const int* __restrict__ dst, int E) {
    int i = blockIdx.x * blockDim.x + threadIdx.x;
    if (i < E) {
        int d = dst[i];
        int pos = g_off[d] + atomicAdd(&g_cur[d], 1);
        g_csr[pos] = src[i];
    }
}

__global__ void gmin_kernel(const int* __restrict__ batch, int n) {
    int i = blockIdx.x * blockDim.x + threadIdx.x;
    if (i < n) atomicMin(&g_gstart[batch[i]], i);
}

__global__ void gfix_kernel(int n) {
    if (threadIdx.x == 0 && blockIdx.x == 0) {
        g_gstart[NGRAPHS] = n;
        for (int g = NGRAPHS - 1; g >= 0; g--)
            if (g_gstart[g] > g_gstart[g + 1]) g_gstart[g] = g_gstart[g + 1];
    }
}

// ---------------------------------------------------------------------------
// fp16 tensor-core GEMM (fp32 accumulate): g_hh = A @ B, C stored fp16.
// Template: HA=true -> A is fp16 (g_aggh, direct uint4 copy);
//           HA=false -> A is fp32 (x, cvt on the fly).
// B is always pre-converted fp16 weights.
// CTA tile 128x128x32, 8 warps, warp tile 32x64 via m16n8k16 + ldmatrix.
// ---------------------------------------------------------------------------
#define TBM 128
#define TBN 128
#define TBK 32
#define APADH 8     // Ah row = 40 half = 80 B
#define BPADH 8     // Bh row = 136 half = 272 B
#define AROW (TBK + APADH)
#define BROW (TBN + BPADH)

__device__ __forceinline__ void ldsm_x4(uint32_t& r0, uint32_t& r1,
                                        uint32_t& r2, uint32_t& r3, uint32_t addr) {
    asm volatile("ldmatrix.sync.aligned.m8n8.x4.shared.b16 {%0,%1,%2,%3}, [%4];"
                 : "=r"(r0), "=r"(r1), "=r"(r2), "=r"(r3) : "r"(addr));
}

__device__ __forceinline__ void ldsm_x4_t(uint32_t& r0, uint32_t& r1,
                                          uint32_t& r2, uint32_t& r3, uint32_t addr) {
    asm volatile("ldmatrix.sync.aligned.m8n8.x4.trans.shared.b16 {%0,%1,%2,%3}, [%4];"
                 : "=r"(r0), "=r"(r1), "=r"(r2), "=r"(r3) : "r"(addr));
}

__device__ __forceinline__ void mma_f16(float* c, const uint32_t* a, const uint32_t* b) {
    asm volatile(
        "mma.sync.aligned.m16n8k16.row.col.f32.f16.f16.f32 "
        "{%0,%1,%2,%3}, {%4,%5,%6,%7}, {%8,%9}, {%0,%1,%2,%3};"
        : "+f"(c[0]), "+f"(c[1]), "+f"(c[2]), "+f"(c[3])
        : "r"(a[0]), "r"(a[1]), "r"(a[2]), "r"(a[3]), "r"(b[0]), "r"(b[1]));
}

__device__ __forceinline__ uint2 pack4h(float4 v) {
    __half2 h0 = __floats2half2_rn(v.x, v.y);
    __half2 h1 = __floats2half2_rn(v.z, v.w);
    uint2 u;
    u.x = *(uint32_t*)&h0;
    u.y = *(uint32_t*)&h1;
    return u;
}

template <bool HA>
__global__ __launch_bounds__(256)
void gemm_tc_kernel(const float* __restrict__ Af, const __half* __restrict__ Ahg,
                    const __half* __restrict__ Bg, int M, int K, int N) {
    __half* __restrict__ C = g_hh;

    __shared__ __align__(16) __half Ah[2][TBM][AROW];
    __shared__ __align__(16) __half Bh[2][TBK][BROW];

    const int tid  = threadIdx.x;
    const int warp = tid >> 5;
    const int lane = tid & 31;
    const int g    = lane >> 2;
    const int t    = lane & 3;
    const int wm   = warp >> 1;
    const int wn   = warp & 1;
    const int row0 = blockIdx.y * TBM;
    const int col0 = blockIdx.x * TBN;
    const int mbase = wm * 32;
    const int nbase = wn * 64;

    const int lquad = lane & 15;
    const int lhalf = (lane >> 4) << 3;

    const uint32_t a_smem0 = (uint32_t)__cvta_generic_to_shared(&Ah[0][0][0]);
    const uint32_t b_smem0 = (uint32_t)__cvta_generic_to_shared(&Bh[0][0][0]);
    const uint32_t a_buf_sz = TBM * AROW * 2;
    const uint32_t b_buf_sz = TBK * BROW * 2;

    float acc[2][8][4];
    #pragma unroll
    for (int mi = 0; mi < 2; mi++)
        #pragma unroll
        for (int ni = 0; ni < 8; ni++)
            #pragma unroll
            for (int r = 0; r < 4; r++) acc[mi][ni][r] = 0.f;

    // ---- prologue: tile 0 -> buf 0 ----
    if (HA) {
        #pragma unroll
        for (int l = 0; l < 2; l++) {
            int p = tid + l * 256;               // 0..511
            int r = p >> 2, c8 = p & 3;
            int gr = row0 + r;
            uint4 v = make_uint4(0, 0, 0, 0);
            if (gr < M) v = *(const uint4*)&Ahg[(size_t)gr * K + c8 * 8];
            *(uint4*)&Ah[0][r][c8 * 8] = v;
        }
    } else {
        #pragma unroll
        for (int l = 0; l < 4; l++) {
            int p  = tid + l * 256;
            int r  = p >> 3, c4 = p & 7;
            int gr = row0 + r;
            float4 v = make_float4(0.f, 0.f, 0.f, 0.f);
            if (gr < M) v = *(const float4*)&Af[(size_t)gr * K + c4 * 4];
            *(uint2*)&Ah[0][r][c4 * 4] = pack4h(v);
        }
    }
    #pragma unroll
    for (int l = 0; l < 2; l++) {
        int p = tid + l * 256;                   // 0..511
        int r = p >> 4, c8 = p & 15;
        uint4 v = *(const uint4*)&Bg[(size_t)r * N + col0 + c8 * 8];
        *(uint4*)&Bh[0][r][c8 * 8] = v;
    }
    __syncthreads();

    int buf = 0;
    for (int k0 = 0; k0 < K; k0 += TBK) {
        const int kn = k0 + TBK;
        const bool has_next = kn < K;

        // ---- prefetch next tile into registers ----
        uint4  pah[2];
        float4 paf[4];
        uint4  pbh[2];
        if (has_next) {
            if (HA) {
                #pragma unroll
                for (int l = 0; l < 2; l++) {
                    int p = tid + l * 256;
                    int r = p >> 2, c8 = p & 3;
                    int gr = row0 + r;
                    pah[l] = make_uint4(0, 0, 0, 0);
                    if (gr < M) pah[l] = *(const uint4*)&Ahg[(size_t)gr * K + kn + c8 * 8];
                }
            } else {
                #pragma unroll
                for (int l = 0; l < 4; l++) {
                    int p = tid + l * 256;
                    int r = p >> 3, c4 = p & 7;
                    int gr = row0 + r;
                    paf[l] = make_float4(0.f, 0.f, 0.f, 0.f);
                    if (gr < M) paf[l] = *(const float4*)&Af[(size_t)gr * K + kn + c4 * 4];
                }
            }
            #pragma unroll
            for (int l = 0; l < 2; l++) {
                int p = tid + l * 256;
                int r = p >> 4, c8 = p & 15;
                pbh[l] = *(const uint4*)&Bg[(size_t)(kn + r) * N + col0 + c8 * 8];
            }
        }

        // ---- compute current buffer: 2 x k16 ----
        const uint32_t a_base = a_smem0 + buf * a_buf_sz;
        const uint32_t b_base = b_smem0 + buf * b_buf_sz;
        #pragma unroll
        for (int k16 = 0; k16 < 2; k16++) {
            const int kk = k16 * 16;
            uint32_t a[2][4];
            #pragma unroll
            for (int mi = 0; mi < 2; mi++) {
                uint32_t addr = a_base +
                    ((mbase + mi * 16 + lquad) * AROW + kk + lhalf) * 2;
                ldsm_x4(a[mi][0], a[mi][1], a[mi][2], a[mi][3], addr);
            }
            uint32_t b[8][2];
            #pragma unroll
            for (int pr = 0; pr < 4; pr++) {
                uint32_t addr = b_base +
                    ((kk + lquad) * BROW + nbase + pr * 16 + lhalf) * 2;
                ldsm_x4_t(b[pr * 2][0], b[pr * 2][1],
                          b[pr * 2 + 1][0], b[pr * 2 + 1][1], addr);
            }
            #pragma unroll
            for (int mi = 0; mi < 2; mi++)
                #pragma unroll
                for (int ni = 0; ni < 8; ni++)
                    mma_f16(acc[mi][ni], a[mi], b[ni]);
        }

        // ---- store next tile ----
        if (has_next) {
            int nb_ = buf ^ 1;
            if (HA) {
                #pragma unroll
                for (int l = 0; l < 2; l++) {
                    int p = tid + l * 256;
                    int r = p >> 2, c8 = p & 3;
                    *(uint4*)&Ah[nb_][r][c8 * 8] = pah[l];
                }
            } else {
                #pragma unroll
                for (int l = 0; l < 4; l++) {
                    int p = tid + l * 256;
                    int r = p >> 3, c4 = p & 7;
                    *(uint2*)&Ah[nb_][r][c4 * 4] = pack4h(paf[l]);
                }
            }
            #pragma unroll
            for (int l = 0; l < 2; l++) {
                int p = tid + l * 256;
                int r = p >> 4, c8 = p & 15;
                *(uint4*)&Bh[nb_][r][c8 * 8] = pbh[l];
            }
        }
        __syncthreads();
        buf ^= 1;
    }

    // ---- epilogue: fp16 C write (half2 per register pair) ----
    #pragma unroll
    for (int mi = 0; mi < 2; mi++) {
        int r_lo = row0 + mbase + mi * 16 + g;
        int r_hi = r_lo + 8;
        #pragma unroll
        for (int ni = 0; ni < 8; ni++) {
            int c = col0 + nbase + ni * 8 + 2 * t;
            if (r_lo < M) {
                __half2 h = __floats2half2_rn(acc[mi][ni][0], acc[mi][ni][1]);
                *(__half2*)&C[(size_t)r_lo * N + c] = h;
            }
            if (r_hi < M) {
                __half2 h = __floats2half2_rn(acc[mi][ni][2], acc[mi][ni][3]);
                *(__half2*)&C[(size_t)r_hi * N + c] = h;
            }
        }
    }
}

// ---------------------------------------------------------------------------
// Fused aggregation: warp per node, atomic-free, fp16 gather, fp32 accumulate.
// Each lane owns 8 half (one uint4) of the 256-wide feature row.
// ---------------------------------------------------------------------------
__device__ __forceinline__ void acc8(float* f, uint4 u, float nm) {
    const __half2* h = (const __half2*)&u;
    #pragma unroll
    for (int j = 0; j < 4; j++) {
        float2 v = __half22float2(h[j]);
        f[j * 2]     += v.x * nm;
        f[j * 2 + 1] += v.y * nm;
    }
}

__global__ __launch_bounds__(256)
void node_agg_kernel(const float4* __restrict__ bias, int n, int do_relu) {
    int node = (blockIdx.x * blockDim.x + threadIdx.x) >> 5;
    if (node >= n) return;
    int lane = threadIdx.x & 31;

    const uint4* __restrict__ hh = (const uint4*)g_hh;   // 32 uint4 per row
    const int beg = g_off[node];
    const int end = g_off[node + 1];
    const float dn = g_dinv[node];

    float f[8];
    #pragma unroll
    for (int j = 0; j < 8; j++) f[j] = 0.f;

    int e = beg;
    for (; e + 2 <= end; e += 2) {
        int s0 = g_csr[e];
        int s1 = g_csr[e + 1];
        float nm0 = dn * g_dinv[s0];
        float nm1 = dn * g_dinv[s1];
        uint4 u0 = hh[(size_t)s0 * DH8 + lane];
        uint4 u1 = hh[(size_t)s1 * DH8 + lane];
        acc8(f, u0, nm0);
        acc8(f, u1, nm1);
    }
    if (e < end) {
        int s = g_csr[e];
        float nm = dn * g_dinv[s];
        uint4 u = hh[(size_t)s * DH8 + lane];
        acc8(f, u, nm);
    }

    // self loop + bias
    {
        uint4 u = hh[(size_t)node * DH8 + lane];
        acc8(f, u, dn * dn);
        float4 b0 = bias[lane * 2];
        float4 b1 = bias[lane * 2 + 1];
        f[0] += b0.x; f[1] += b0.y; f[2] += b0.z; f[3] += b0.w;
        f[4] += b1.x; f[5] += b1.y; f[6] += b1.z; f[7] += b1.w;
    }

    if (do_relu) {
        #pragma unroll
        for (int j = 0; j < 8; j++) f[j] = fmaxf(f[j], 0.f);
    }

    // write fp16
    uint4 o;
    __half2* oh = (__half2*)&o;
    #pragma unroll
    for (int j = 0; j < 4; j++)
        oh[j] = __floats2half2_rn(f[j * 2], f[j * 2 + 1]);
    ((uint4*)g_aggh)[(size_t)node * DH8 + lane] = o;
}

// ---------------------------------------------------------------------------
// Mean pool: 4 CTAs per graph, fp16 input, fp32 atomics into g_pool.
// 128 threads; thread c owns feature pair (2c, 2c+1).
// ---------------------------------------------------------------------------
#define POOL_SPLIT 4

__global__ __launch_bounds__(128)
void pool_kernel() {
    int g = blockIdx.x >> 2;
    int p = blockIdx.x & 3;
    int c = threadIdx.x;                      // 0..127
    int beg = g_gstart[g], end = g_gstart[g + 1];
    int len = end - beg;
    int chunk = (len + POOL_SPLIT - 1) / POOL_SPLIT;
    int lo = beg + p * chunk;
    int hi = min(lo + chunk, end);
    if (lo >= hi) return;
    const uint32_t* ah = (const uint32_t*)g_aggh;  // 128 half2 per row
    float ax = 0.f, ay = 0.f;
    for (int i = lo; i < hi; i++) {
        uint32_t u = ah[(size_t)i * 128 + c];
        float2 v = __half22float2(*(__half2*)&u);
        ax += v.x; ay += v.y;
    }
    atomicAdd(&g_pool[g * DHID + 2 * c],     ax);
    atomicAdd(&g_pool[g * DHID + 2 * c + 1], ay);
}

// ---------------------------------------------------------------------------
// Final linear (mean division folded in)
// ---------------------------------------------------------------------------
__global__ __launch_bounds__(256)
void final_kernel(const float* __restrict__ Wl, const float* __restrict__ bl,
                  float* __restrict__ out) {
    int d = blockIdx.x * blockDim.x + threadIdx.x;
    int g = blockIdx.y;
    const float* pg = g_pool + g * DHID;
    float acc = 0.f;
    #pragma unroll 8
    for (int c = 0; c < DHID; c++)
        acc += pg[c] * Wl[(size_t)c * DIN + d];
    float cnt = (float)(g_gstart[g + 1] - g_gstart[g]);
    out[(size_t)g * DIN + d] = acc / fmaxf(cnt, 1.f) + bl[d];
}

// ---------------------------------------------------------------------------
// Launch.  Layer-1 GEMM stays the 4th launch so ncu profiles it.
// ---------------------------------------------------------------------------
extern "C" void kernel_launch(void* const* d_in, const int* in_sizes, int n_in,
                              void* d_out, int out_size) {
    const float* x     = (const float*)d_in[0];
    const int*   ei    = (const int*)d_in[1];
    const int*   batch = (const int*)d_in[2];
    const float* W1 = (const float*)d_in[3];
    const float* b1 = (const float*)d_in[4];
    const float* W2 = (const float*)d_in[5];
    const float* b2 = (const float*)d_in[6];
    const float* W3 = (const float*)d_in[7];
    const float* b3 = (const float*)d_in[8];
    const float* Wl = (const float*)d_in[9];
    const float* bl = (const float*)d_in[10];
    float* out = (float*)d_out;

    const int n = in_sizes[0] / DIN;       // 50000
    const int E = in_sizes[1] / 2;         // 800000
    const int* src = ei;
    const int* dst = ei + E;

    dim3 gemm_grid(DHID / TBN, (n + TBM - 1) / TBM);
    const int agg_grid = (n * 32 + 255) / 256;
    const int nb = (n + 1023) / 1024;
    const int init_threads = DIN * DHID;                 // covers all init tasks

    __half *w1h, *w2h, *w3h, *aggh;
    cudaGetSymbolAddress((void**)&w1h,  g_w1h);
    cudaGetSymbolAddress((void**)&w2h,  g_w2h);
    cudaGetSymbolAddress((void**)&w3h,  g_w3h);
    cudaGetSymbolAddress((void**)&aggh, g_aggh);

    // launches 1-3
    init_kernel<<<(init_threads + 255) / 256, 256>>>(W1, W2, W3, n);
    hist_kernel<<<(E + 255) / 256, 256>>>(dst, E);
    dinv_kernel<<<(n + 255) / 256, 256>>>(n);

    // launch 4: layer-1 GEMM (fp32 A path; profiled by ncu)
    gemm_tc_kernel<false><<<gemm_grid, 256>>>(x, (const __half*)nullptr, w1h,
                                              n, DIN, DHID);

    // CSR build
    scan1_kernel<<<nb, 1024>>>(n);
    scan2_kernel<<<1, 32>>>(nb, n);
    scan3_kernel<<<nb, 1024>>>(n);
    scatter_kernel<<<(E + 255) / 256, 256>>>(src, dst, E);
    gmin_kernel<<<(n + 255) / 256, 256>>>(batch, n);
    gfix_kernel<<<1, 32>>>(n);

    // layer 1 aggregation
    node_agg_kernel<<<agg_grid, 256>>>((const float4*)b1, n, 1);

    // layer 2 (fp16 A path)
    gemm_tc_kernel<true><<<gemm_grid, 256>>>(nullptr, aggh, w2h, n, DHID, DHID);
    node_agg_kernel<<<agg_grid, 256>>>((const float4*)b2, n, 1);

    // layer 3 (no relu)
    gemm_tc_kernel<true><<<gemm_grid, 256>>>(nullptr, aggh, w3h, n, DHID, DHID);
    node_agg_kernel<<<agg_grid, 256>>>((const float4*)b3, n, 0);

    // mean pool + head
    pool_kernel<<<NGRAPHS * POOL_SPLIT, 128>>>();
    dim3 fgrid(DIN / 256, NGRAPHS);
    final_kernel<<<fgrid, 256>>>(Wl, bl, out);
}